// round 16
// baseline (speedup 1.0000x reference)
#include <cuda_runtime.h>
#include <cuda_fp16.h>
#include <math.h>
#include <stdint.h>

#define T_STEPS 2048
#define ISZ 256
#define HSZ 512
#define BSZ 64
#define NB 128          // pre-phase blocks
#define NB2 64          // recurrent blocks
#define TPB 256
#define BN_EPS 1e-5f

// ---- SMEM layout (bytes) ----
// pre-phase:
#define SM_PW 0          // 128 rows x 260 floats = 133120 B
#define SM_PX 133120     // 256 rows x 72 floats  = 73728 B  -> end 206848
// recurrent phase (overlaps pre-phase region; separated by grid barrier):
#define SM_H      0      // 64 cols x 520 halves = 66560 B
#define SM_WP     66560  // permuted W fragments: 2 mtiles x 4096 words = 32768 -> 99328
#define SM_SPILL  99328  // 32 rows x 68 floats = 8704 -> 108032
#define SM_BNB    108032 // 2 x 32 x 64 floats = 16384 -> 124416
#define SM_HOUT   124416 // 64 cols x 8 halves = 1024 -> 125440
// params:
#define SM_PAR    206848
#define SMEM_BYTES 207872

#define SPILL_STR 68
#define HSTR_W 260        // H row stride in 32-bit words (520 halves)

struct Par {
    float gh[32], bh[32];
    float gc[8], bc[8];
    float csum[16], csq[16];
};

// ---- device globals (static, no allocation) ----
__device__ __half g_h16[2][BSZ * HSZ];       // h fp16, batch-major [col][hidden]
__device__ float g_bnb[268435456];           // [t][2048 rows][64]: BN(Wih@x)+bias
__device__ unsigned long long g_arrive = 0ULL;
__device__ volatile unsigned long long g_release = 0ULL;
__device__ unsigned long long g_arrive2 = 0ULL;
__device__ volatile unsigned long long g_release2 = 0ULL;

// ---- helpers ----
__device__ __forceinline__ void cp_async16(void* smem_dst, const void* gsrc) {
    unsigned s;
    asm("{ .reg .u64 t; cvta.to.shared.u64 t, %1; cvt.u32.u64 %0, t; }"
        : "=r"(s) : "l"(smem_dst));
    asm volatile("cp.async.cg.shared.global [%0], [%1], 16;" :: "r"(s), "l"(gsrc));
}
__device__ __forceinline__ void cp_commit() { asm volatile("cp.async.commit_group;"); }
template <int N>
__device__ __forceinline__ void cp_wait() { asm volatile("cp.async.wait_group %0;" :: "n"(N)); }

// m16n8k8 tf32 HMMA (pre-phase)
__device__ __forceinline__ void mma8(float* d, uint32_t a0, uint32_t a1, uint32_t a2,
                                     uint32_t a3, uint32_t b0, uint32_t b1) {
    asm volatile(
        "mma.sync.aligned.m16n8k8.row.col.f32.tf32.tf32.f32 "
        "{%0,%1,%2,%3}, {%4,%5,%6,%7}, {%8,%9}, {%0,%1,%2,%3};"
        : "+f"(d[0]), "+f"(d[1]), "+f"(d[2]), "+f"(d[3])
        : "r"(a0), "r"(a1), "r"(a2), "r"(a3), "r"(b0), "r"(b1));
}
// m16n8k16 f16 HMMA (recurrent loop)
__device__ __forceinline__ void mma16(float* d, uint32_t a0, uint32_t a1, uint32_t a2,
                                      uint32_t a3, uint32_t b0, uint32_t b1) {
    asm volatile(
        "mma.sync.aligned.m16n8k16.row.col.f32.f16.f16.f32 "
        "{%0,%1,%2,%3}, {%4,%5,%6,%7}, {%8,%9}, {%0,%1,%2,%3};"
        : "+f"(d[0]), "+f"(d[1]), "+f"(d[2]), "+f"(d[3])
        : "r"(a0), "r"(a1), "r"(a2), "r"(a3), "r"(b0), "r"(b1));
}
__device__ __forceinline__ uint32_t fb(float v) { return __float_as_uint(v); }

__device__ __forceinline__ float sigm(float x) { return 1.0f / (1.0f + __expf(-x)); }
__device__ __forceinline__ float tanh_fast(float x) {
    return 2.0f / (1.0f + __expf(-2.0f * x)) - 1.0f;
}

// ticket barriers (R10 style; best measured)
__device__ __forceinline__ void grid_barrier_pre() {
    __syncthreads();
    if (threadIdx.x == 0) {
        __threadfence();
        unsigned long long a = atomicAdd(&g_arrive, 1ULL);
        unsigned long long target = (a / NB + 1ULL) * NB;
        if (a % NB == NB - 1) {
            __threadfence();
            g_release = target;
        } else {
            while (g_release < target) { }
        }
    }
    __syncthreads();
}
__device__ __forceinline__ void grid_barrier_rec() {
    __syncthreads();
    if (threadIdx.x == 0) {
        __threadfence();
        unsigned long long a = atomicAdd(&g_arrive2, 1ULL);
        unsigned long long target = (a / NB2 + 1ULL) * NB2;
        if (a % NB2 == NB2 - 1) {
            __threadfence();
            g_release2 = target;
        } else {
            while (g_release2 < target) { }
        }
    }
    __syncthreads();
}

// ---------------- kernel ----------------
__global__ void __launch_bounds__(TPB, 1)
bn_lstm_mma(const float* __restrict__ x,
            const float* __restrict__ wih,
            const float* __restrict__ whh,
            const float* __restrict__ bias,
            const float* __restrict__ gih, const float* __restrict__ bih,
            const float* __restrict__ ghh, const float* __restrict__ bhh,
            const float* __restrict__ gcc, const float* __restrict__ bcc,
            float* __restrict__ out)
{
    extern __shared__ char sm[];
    Par* P = (Par*)(sm + SM_PAR);

    const int tid  = threadIdx.x;
    const int wid  = tid >> 5;
    const int lane = tid & 31;
    const int bid  = blockIdx.x;
    const int gq   = lane >> 2;       // fragment row group 0..7
    const int tq   = lane & 3;        // fragment k/col group 0..3
    const int col = tid & 63;
    const int jj  = (tid >> 6) & 3;

    // zero h[0]: 128 blocks x 4 hidden rows (old mapping covers 512 rows)
    g_h16[0][col * HSZ + 4 * bid + jj] = __float2half(0.0f);

    // ================= PRE-PHASE (all 128 blocks): g_bnb = BN(Wih@x)+bias ======
    {
        float* PW = (float*)(sm + SM_PW);
        float* PX = (float*)(sm + SM_PX);
        for (int mc = 0; mc < 16; ++mc) {
            const int rbase = mc * 128;
            __syncthreads();
            #pragma unroll
            for (int i = 0; i < 32; ++i) {
                int e = tid + i * TPB;
                int r = e >> 6, q = e & 63;
                cp_async16(&PW[r * 260 + q * 4],
                           wih + ((size_t)(rbase + r)) * 256 + q * 4);
            }
            cp_commit();

            for (int tt = 0; tt < 16; ++tt) {
                const int t = bid * 16 + tt;
                #pragma unroll
                for (int i = 0; i < 16; ++i) {
                    int e = tid + i * TPB;
                    int r = e >> 4, q = e & 15;
                    cp_async16(&PX[r * 72 + q * 4],
                               x + ((size_t)t * 256 + r) * 64 + q * 4);
                }
                cp_commit();
                cp_wait<0>();
                __syncthreads();

                float acc[8][4];
                #pragma unroll
                for (int nt = 0; nt < 8; ++nt)
                    #pragma unroll
                    for (int i = 0; i < 4; ++i) acc[nt][i] = 0.0f;

                const float* WA = PW + (wid * 16) * 260;
                #pragma unroll 4
                for (int ks = 0; ks < 32; ++ks) {
                    int k = ks * 8 + tq;
                    uint32_t a0 = fb(WA[gq * 260 + k]);
                    uint32_t a1 = fb(WA[(gq + 8) * 260 + k]);
                    uint32_t a2 = fb(WA[gq * 260 + k + 4]);
                    uint32_t a3 = fb(WA[(gq + 8) * 260 + k + 4]);
                    #pragma unroll
                    for (int nt = 0; nt < 8; ++nt) {
                        uint32_t b0 = fb(PX[k * 72 + nt * 8 + gq]);
                        uint32_t b1 = fb(PX[(k + 4) * 72 + nt * 8 + gq]);
                        mma8(acc[nt], a0, a1, a2, a3, b0, b1);
                    }
                }

                int row0 = rbase + wid * 16 + gq;
                int row1 = row0 + 8;
                float s0 = 0, q0 = 0, s1 = 0, q1 = 0;
                #pragma unroll
                for (int nt = 0; nt < 8; ++nt) {
                    s0 += acc[nt][0] + acc[nt][1];
                    q0 += acc[nt][0] * acc[nt][0] + acc[nt][1] * acc[nt][1];
                    s1 += acc[nt][2] + acc[nt][3];
                    q1 += acc[nt][2] * acc[nt][2] + acc[nt][3] * acc[nt][3];
                }
                #pragma unroll
                for (int off = 1; off < 4; off <<= 1) {
                    s0 += __shfl_xor_sync(0xffffffffu, s0, off);
                    q0 += __shfl_xor_sync(0xffffffffu, q0, off);
                    s1 += __shfl_xor_sync(0xffffffffu, s1, off);
                    q1 += __shfl_xor_sync(0xffffffffu, q1, off);
                }
                float mu0 = s0 * (1.0f / 64.0f);
                float v0  = q0 * (1.0f / 64.0f) - mu0 * mu0;
                float sc0 = rsqrtf(v0 + BN_EPS) * gih[row0];
                float sh0 = bih[row0] - mu0 * sc0 + bias[row0];
                float mu1 = s1 * (1.0f / 64.0f);
                float v1  = q1 * (1.0f / 64.0f) - mu1 * mu1;
                float sc1 = rsqrtf(v1 + BN_EPS) * gih[row1];
                float sh1 = bih[row1] - mu1 * sc1 + bias[row1];

                float* d0 = g_bnb + ((size_t)t * 2048 + row0) * 64;
                float* d1 = g_bnb + ((size_t)t * 2048 + row1) * 64;
                #pragma unroll
                for (int nt = 0; nt < 8; ++nt) {
                    *(float2*)&d0[nt * 8 + 2 * tq] =
                        make_float2(acc[nt][0] * sc0 + sh0, acc[nt][1] * sc0 + sh0);
                    *(float2*)&d1[nt * 8 + 2 * tq] =
                        make_float2(acc[nt][2] * sc1 + sh1, acc[nt][3] * sc1 + sh1);
                }
                __syncthreads();
            }
        }
    }

    grid_barrier_pre();
    if (bid >= NB2) return;           // recurrent phase: 64 blocks only

    // ---------- recurrent-phase setup (block owns 8 hidden rows) ----------
    const int j0 = 8 * bid;
    __half*   H16  = (__half*)(sm + SM_H);
    uint32_t* H32  = (uint32_t*)(sm + SM_H);
    uint32_t* WP32 = (uint32_t*)(sm + SM_WP);
    float* SPILL   = (float*)(sm + SM_SPILL);
    float* BNB     = (float*)(sm + SM_BNB);     // double buffer: [2][32*64]
    __half* HOUT   = (__half*)(sm + SM_HOUT);   // [64 cols][8 rows]

    if (tid < 32) {
        int grow = 512 * (tid >> 3) + j0 + (tid & 7);
        P->gh[tid] = ghh[grow]; P->bh[tid] = bhh[grow];
    }
    if (tid < 8) { P->gc[tid] = gcc[j0 + tid]; P->bc[tid] = bcc[j0 + tid]; }

    // permuted W fragments: 2 m-tiles x [ks][lane][4 words]
    for (int i = tid; i < 8192; i += TPB) {
        int mt = i >> 12;
        int r4 = i & 4095;
        int ks = r4 >> 7, ln = (r4 >> 2) & 31, j = r4 & 3;
        int g2 = ln >> 2, t2 = ln & 3;
        int lt = g2 + 8 * (j & 1);                // tile row 0..15
        int L  = mt * 16 + lt;                    // local gate row 0..31
        int hc = 16 * ks + 2 * t2 + 8 * (j >> 1); // half-column (k index)
        int grow = 512 * (L >> 3) + j0 + (L & 7);
        __half2 hh = __floats2half2_rn(whh[(size_t)grow * 512 + hc],
                                       whh[(size_t)grow * 512 + hc + 1]);
        WP32[i] = *(uint32_t*)&hh;
    }
    __syncthreads();

    // initial BNB(0) prefetch
    #pragma unroll
    for (int i = 0; i < 2; ++i) {
        int e = tid + i * TPB;
        int l = e >> 4, q = e & 15;
        int grow = 512 * (l >> 3) + j0 + (l & 7);
        cp_async16(&BNB[l * 64 + q * 4],
                   g_bnb + ((size_t)0 * 2048 + grow) * 64 + q * 4);
    }
    cp_commit();

    // per-warp h load mapping: warp wid owns batch rows 8*wid .. 8*wid+7
    const int lrow = 8 * wid + (lane >> 2);
    const int loff = (lane & 3);
    const int nrow260 = (wid * 8 + gq) * HSTR_W;
    const __half* hgbase0 = g_h16[0];
    const __half* hgbase1 = g_h16[1];

    // ================= recurrent loop =================
    float c0 = 0.0f, c1 = 0.0f;       // cell states for rows jj, jj+4
    for (int t = 0; t < T_STEPS; ++t) {
        const int p = t & 1;
        const __half* __restrict__ hsrc = p ? hgbase1 : hgbase0;

        // per-warp: 4 chunks of own 8 rows (64B contiguous per 4 lanes)
        #pragma unroll
        for (int c = 0; c < 4; ++c) {
            #pragma unroll
            for (int i = 0; i < 4; ++i) {
                int q8 = (loff + 4 * i) * 8;
                cp_async16(H16 + lrow * 520 + c * 128 + q8,
                           hsrc + lrow * 512 + c * 128 + q8);
            }
            cp_commit();
        }

        // a = Whh @ h: warp = n-tile wid; both m-tiles; 4 accumulator chains
        float a00[4] = {0,0,0,0}, a01[4] = {0,0,0,0};   // m-tile 0, even/odd ks
        float a10[4] = {0,0,0,0}, a11[4] = {0,0,0,0};   // m-tile 1
        #define DO_CHUNK(C)                                                     \
        {                                                                       \
            _Pragma("unroll")                                                   \
            for (int s2 = 0; s2 < 8; ++s2) {                                    \
                int ks = 8 * (C) + s2;                                          \
                uint4 aw0 = *(const uint4*)(WP32 + (ks * 32 + lane) * 4);       \
                uint4 aw1 = *(const uint4*)(WP32 + 4096 + (ks * 32 + lane) * 4);\
                uint32_t b0 = H32[nrow260 + 8 * ks + tq];                       \
                uint32_t b1 = H32[nrow260 + 8 * ks + tq + 4];                   \
                mma16((s2 & 1) ? a01 : a00, aw0.x, aw0.y, aw0.z, aw0.w, b0, b1);\
                mma16((s2 & 1) ? a11 : a10, aw1.x, aw1.y, aw1.z, aw1.w, b0, b1);\
            }                                                                   \
        }
        cp_wait<3>(); __syncwarp(); DO_CHUNK(0);
        cp_wait<2>(); __syncwarp(); DO_CHUNK(1);
        cp_wait<1>(); __syncwarp(); DO_CHUNK(2);
        cp_wait<0>(); __syncwarp(); DO_CHUNK(3);
        #undef DO_CHUNK

        float am0[4], am1[4];
        #pragma unroll
        for (int i = 0; i < 4; ++i) { am0[i] = a00[i] + a01[i]; am1[i] = a10[i] + a11[i]; }

        // spill D
        *(float2*)&SPILL[gq * SPILL_STR + wid * 8 + 2 * tq] =
            make_float2(am0[0], am0[1]);
        *(float2*)&SPILL[(gq + 8) * SPILL_STR + wid * 8 + 2 * tq] =
            make_float2(am0[2], am0[3]);
        *(float2*)&SPILL[(16 + gq) * SPILL_STR + wid * 8 + 2 * tq] =
            make_float2(am1[0], am1[1]);
        *(float2*)&SPILL[(24 + gq) * SPILL_STR + wid * 8 + 2 * tq] =
            make_float2(am1[2], am1[3]);
        __syncthreads();

        // warp-local BN(a): 8 rows this warp's epilogue needs
        float sc8[8], sh8[8];
        #pragma unroll
        for (int g = 0; g < 4; ++g) {
            #pragma unroll
            for (int rr = 0; rr < 2; ++rr) {
                int r = g * 8 + jj + 4 * rr;
                float x0 = SPILL[r * SPILL_STR + lane];
                float x1 = SPILL[r * SPILL_STR + 32 + lane];
                float sa = x0 + x1, qa = x0 * x0 + x1 * x1;
                #pragma unroll
                for (int off = 16; off; off >>= 1) {
                    sa += __shfl_xor_sync(0xffffffffu, sa, off);
                    qa += __shfl_xor_sync(0xffffffffu, qa, off);
                }
                float mu = sa * (1.0f / 64.0f);
                float var = qa * (1.0f / 64.0f) - mu * mu;
                float sc = rsqrtf(var + BN_EPS) * P->gh[r];
                sc8[g + 4 * rr] = sc;
                sh8[g + 4 * rr] = P->bh[r] - mu * sc;
            }
        }

        // gates + cell for rows jj and jj+4
        const float* BNBt = BNB + (t & 1) * 2048;
        float pre0[4], pre1[4];
        #pragma unroll
        for (int g = 0; g < 4; ++g) {
            int L0 = g * 8 + jj;
            int L1 = L0 + 4;
            pre0[g] = SPILL[L0 * SPILL_STR + col] * sc8[g] + sh8[g]
                    + BNBt[L0 * 64 + col];
            pre1[g] = SPILL[L1 * SPILL_STR + col] * sc8[g + 4] + sh8[g + 4]
                    + BNBt[L1 * 64 + col];
        }
        float cn0, cn1, go0, go1;
        {
            float gi_ = sigm(pre0[0]), gf_ = sigm(pre0[1]);
            float gg_ = tanh_fast(pre0[2]);
            go0 = sigm(pre0[3]);
            cn0 = gf_ * c0 + gi_ * gg_; c0 = cn0;
        }
        {
            float gi_ = sigm(pre1[0]), gf_ = sigm(pre1[1]);
            float gg_ = tanh_fast(pre1[2]);
            go1 = sigm(pre1[3]);
            cn1 = gf_ * c1 + gi_ * gg_; c1 = cn1;
        }

        {
            float s0 = cn0, q0 = cn0 * cn0, s1 = cn1, q1 = cn1 * cn1;
            #pragma unroll
            for (int off = 16; off; off >>= 1) {
                s0 += __shfl_xor_sync(0xffffffffu, s0, off);
                q0 += __shfl_xor_sync(0xffffffffu, q0, off);
                s1 += __shfl_xor_sync(0xffffffffu, s1, off);
                q1 += __shfl_xor_sync(0xffffffffu, q1, off);
            }
            if (lane == 0) {
                P->csum[2 * wid] = s0;     P->csq[2 * wid] = q0;
                P->csum[2 * wid + 1] = s1; P->csq[2 * wid + 1] = q1;
            }
        }
        __syncthreads();
        // fused BN(c) + h for both rows
        {
            float S0 = P->csum[4 * jj] + P->csum[4 * jj + 2];
            float Q0 = P->csq[4 * jj] + P->csq[4 * jj + 2];
            float S1 = P->csum[4 * jj + 1] + P->csum[4 * jj + 3];
            float Q1 = P->csq[4 * jj + 1] + P->csq[4 * jj + 3];
            float mu0 = S0 * (1.0f / 64.0f);
            float v0  = Q0 * (1.0f / 64.0f) - mu0 * mu0;
            float sc0 = rsqrtf(v0 + BN_EPS) * P->gc[jj];
            float sh0 = P->bc[jj] - mu0 * sc0;
            float mu1 = S1 * (1.0f / 64.0f);
            float v1  = Q1 * (1.0f / 64.0f) - mu1 * mu1;
            float sc1 = rsqrtf(v1 + BN_EPS) * P->gc[jj + 4];
            float sh1 = P->bc[jj + 4] - mu1 * sc1;
            float hv0 = go0 * tanh_fast(cn0 * sc0 + sh0);
            float hv1 = go1 * tanh_fast(cn1 * sc1 + sh1);
            HOUT[col * 8 + jj]     = __float2half(hv0);
            HOUT[col * 8 + jj + 4] = __float2half(hv1);
            out[(size_t)t * (HSZ * BSZ) + (j0 + jj) * BSZ + col] = hv0;
            out[(size_t)t * (HSZ * BSZ) + (j0 + jj + 4) * BSZ + col] = hv1;
        }

        // BNB(t+1) prefetch (lands during barrier wait)
        {
            int tn = (t + 1 < T_STEPS) ? t + 1 : t;
            #pragma unroll
            for (int i = 0; i < 2; ++i) {
                int e = tid + i * TPB;
                int l = e >> 4, q = e & 15;
                int grow = 512 * (l >> 3) + j0 + (l & 7);
                cp_async16(&BNB[((t + 1) & 1) * 2048 + l * 64 + q * 4],
                           g_bnb + ((size_t)tn * 2048 + grow) * 64 + q * 4);
            }
            cp_commit();
        }

        __syncthreads();    // HOUT staged
        // coalesced h write: 64 threads, 16B each (8 halves per batch col)
        if (tid < 64) {
            uint4 v = ((const uint4*)HOUT)[tid];
            *(uint4*)&(p ? hgbase0 : hgbase1)[tid * HSZ + j0] = v;
        }

        grid_barrier_rec();
    }
}

// ---------------- launch ----------------
extern "C" void kernel_launch(void* const* d_in, const int* in_sizes, int n_in,
                              void* d_out, int out_size) {
    const float* x    = (const float*)d_in[0];
    const float* wih  = (const float*)d_in[1];
    const float* whh  = (const float*)d_in[2];
    const float* bias = (const float*)d_in[3];
    const float* gih  = (const float*)d_in[4];
    const float* bih  = (const float*)d_in[5];
    const float* ghh  = (const float*)d_in[6];
    const float* bhh  = (const float*)d_in[7];
    const float* gcc  = (const float*)d_in[8];
    const float* bcc  = (const float*)d_in[9];
    float* out = (float*)d_out;

    cudaFuncSetAttribute(bn_lstm_mma,
                         cudaFuncAttributeMaxDynamicSharedMemorySize, SMEM_BYTES);
    bn_lstm_mma<<<NB, TPB, SMEM_BYTES>>>(x, wih, whh, bias, gih, bih,
                                         ghh, bhh, gcc, bcc, out);
}